// round 15
// baseline (speedup 1.0000x reference)
#include <cuda_runtime.h>
#include <cstdint>

#define T_STEPS 2000
#define BATCH   256
#define SEQ     10000
#define KW      5
#define NCHUNK  16           // 16 chunks x 128 t (last chunk: 80 real steps)
#define NFLAGS  (NCHUNK * BATCH)
#define NHEAT   148

typedef unsigned long long ull;

// Gate pre-activations a_x[t][b][j], float2 at (t*256+b)*32 + l =
// { a[j=l], a[j=l+32] }. Padded by 2 timesteps for branchless prefetch.
__device__ float g_ax[(size_t)(T_STEPS + 2) * BATCH * 64];
// [0, NFLAGS): producer->consumer chunk flags; [NFLAGS]: scan-done counter
__device__ int g_flag[NFLAGS + 1];
__device__ volatile float g_sink;   // heater result sink (never read)

__device__ __forceinline__ float tanhap(float x) {
    float r; asm("tanh.approx.f32 %0, %1;" : "=f"(r) : "f"(x)); return r;
}

// ---- f32x2 packed helpers ----
__device__ __forceinline__ ull pk2(float lo, float hi) {
    ull r; asm("mov.b64 %0, {%1, %2};" : "=l"(r) : "f"(lo), "f"(hi)); return r;
}
__device__ __forceinline__ void upk2(float& lo, float& hi, ull v) {
    asm("mov.b64 {%0, %1}, %2;" : "=f"(lo), "=f"(hi) : "l"(v));
}
__device__ __forceinline__ ull ffma2(ull a, ull b, ull c) {
    ull r; asm("fma.rn.f32x2 %0, %1, %2, %3;" : "=l"(r) : "l"(a), "l"(b), "l"(c)); return r;
}
__device__ __forceinline__ ull fadd2(ull a, ull b) {
    ull r; asm("add.rn.f32x2 %0, %1, %2;" : "=l"(r) : "l"(a), "l"(b)); return r;
}
__device__ __forceinline__ ull fmul2(ull a, ull b) {
    ull r; asm("mul.rn.f32x2 %0, %1, %2;" : "=l"(r) : "l"(a), "l"(b)); return r;
}

__device__ __forceinline__ float sigf_exact(float x) {
    return __fdividef(1.0f, 1.0f + __expf(-x));
}

// ---- ordered smem access ----
__device__ __forceinline__ uint32_t smem_u32(const void* p) {
    uint32_t a;
    asm("{ .reg .u64 t; cvta.to.shared.u64 t, %1; cvt.u32.u64 %0, t; }"
        : "=r"(a) : "l"(p));
    return a;
}
__device__ __forceinline__ void sts_f32(uint32_t a, float v) {
    asm volatile("st.shared.f32 [%0], %1;" :: "r"(a), "f"(v) : "memory");
}
__device__ __forceinline__ void sts_v2(uint32_t a, float x, float y) {
    asm volatile("st.shared.v2.f32 [%0], {%1, %2};" :: "r"(a), "f"(x), "f"(y) : "memory");
}
__device__ __forceinline__ ull lds_u64(uint32_t a) {
    ull v; asm volatile("ld.shared.b64 %0, [%1];" : "=l"(v) : "r"(a) : "memory"); return v;
}
__device__ __forceinline__ float4 lds_v4(uint32_t a) {
    float4 v;
    asm volatile("ld.shared.v4.f32 {%0, %1, %2, %3}, [%4];"
                 : "=f"(v.x), "=f"(v.y), "=f"(v.z), "=f"(v.w) : "r"(a) : "memory");
    return v;
}

// ---- gpu-scope release/acquire flag ops + L1-bypass load ----
__device__ __forceinline__ int ld_acq(const int* p) {
    int v; asm volatile("ld.acquire.gpu.global.b32 %0, [%1];"
                        : "=r"(v) : "l"(p) : "memory"); return v;
}
__device__ __forceinline__ void st_rel(int* p, int v) {
    asm volatile("st.release.gpu.global.b32 [%0], %1;"
                 :: "l"(p), "r"(v) : "memory");
}
__device__ __forceinline__ float2 ldg_cv_f2(const float2* p) {
    float2 v;
    asm volatile("ld.global.cv.v2.f32 {%0, %1}, [%2];"
                 : "=f"(v.x), "=f"(v.y) : "l"(p) : "memory");
    return v;
}

// ===========================================================================
// Fused kernel: blocks [0,256) scan rows; [256, 256+4096) prepass producers;
// [256+4096, 256+4096+NHEAT) DVFS heaters (keep SM clocks boosted while the
// latency-bound scan tail runs; exit when all 256 scan rows are done).
// ===========================================================================
__global__ void __launch_bounds__(128) fused_kernel(
    const float* __restrict__ x,    const float* __restrict__ Wm,
    const float* __restrict__ bm,   const float* __restrict__ Wc,
    const float* __restrict__ bconv,const float* __restrict__ Wx,
    const float* __restrict__ gx,   const float* __restrict__ bx,
    const float* __restrict__ bg,
    const float* __restrict__ Wh,   const float* __restrict__ gh,
    const float* __restrict__ bh,   const float* __restrict__ gc,
    const float* __restrict__ bc,   const float* __restrict__ Wcls,
    const float* __restrict__ bcls, const float* __restrict__ h0,
    const float* __restrict__ c0,   float* __restrict__ out)
{
    if (blockIdx.x >= 256 + NCHUNK * BATCH) {
        // ===================== HEATER ROLE =====================
        const int* dp = &g_flag[NFLAGS];
        float a = 1.0f + 1e-4f * (float)threadIdx.x;
        const float b = 0.99993f;
        while (ld_acq(dp) < 256) {
            #pragma unroll 16
            for (int i = 0; i < 512; i++)
                a = fmaf(a, b, 1e-20f);
            __nanosleep(400);       // ~50% duty: warm clocks, bounded contention
        }
        g_sink = a;                 // keep the loop alive; never read
        return;
    }

    if (blockIdx.x >= 256) {
        // ===================== PREPASS ROLE =====================
        __shared__ float sP[80], sN[80], sbc[16];
        __shared__ float sWm[16], sbm[16], scmx[16];
        __shared__ int   sbmnz;
        __shared__ float sWcT[80 * 16];
        __shared__ ull sWxT2[16][32];
        __shared__ ull sgx2[32], sbxg2[32];
        __shared__ float2 stage[4][32][33];

        int pb = blockIdx.x - 256;
        int cx = pb >> 8;          // chunk 0..15
        int b  = pb & 255;         // batch row

        if (threadIdx.x == 0) {
            int nz = 0;
            for (int i = 0; i < 16; i++) if (bm[i] != 0.0f) nz = 1;
            sbmnz = nz;
        }
        if (threadIdx.x < 80) {
            int o = threadIdx.x / 5, k = threadIdx.x % 5;
            float p = 0.0f, n = 0.0f;
            for (int i = 0; i < 16; i++) {
                float w = __ldg(&Wm[i]);
                float c = __ldg(&Wc[o * 80 + i * 5 + k]);
                if (w > 0.0f) p = fmaf(c, w, p);
                else if (w < 0.0f) n = fmaf(c, w, n);
            }
            sP[threadIdx.x] = p;
            sN[threadIdx.x] = n;
        }
        if (threadIdx.x >= 96 && threadIdx.x < 112) {
            int col = threadIdx.x - 96;
            float s = 0.0f;
            for (int j = 0; j < 64; j++) s += __ldg(&Wx[j * 16 + col]);
            scmx[col] = s * (1.0f / 64.0f);
        }
        for (int i = threadIdx.x; i < 16; i += blockDim.x) {
            sbc[i] = bconv[i]; sWm[i] = Wm[i]; sbm[i] = bm[i];
        }
        for (int i = threadIdx.x; i < 80 * 16; i += blockDim.x) {
            int ik = i >> 4, o = i & 15;
            sWcT[i] = Wc[o * 80 + ik];
        }
        for (int i = threadIdx.x; i < 32; i += blockDim.x) {
            sgx2[i]  = pk2(gx[i], gx[i + 32]);
            sbxg2[i] = pk2(bx[i] + bg[i], bx[i + 32] + bg[i + 32]);
        }
        __syncthreads();

        for (int i = threadIdx.x; i < 16 * 32; i += blockDim.x) {
            int o = i >> 5, l = i & 31;
            sWxT2[o][l] = pk2(Wx[l * 16 + o] - scmx[o],
                              Wx[(l + 32) * 16 + o] - scmx[o]);
        }
        __syncthreads();

        const int bmnz = sbmnz;
        int lane = threadIdx.x & 31;
        int wrp  = threadIdx.x >> 5;
        int tbase = cx * 128 + wrp * 32;
        int t     = tbase + lane;
        int tt = (t < T_STEPS) ? t : 0;

        float xt[16];
        #pragma unroll
        for (int o = 0; o < 16; o++) xt[o] = sbc[o];

        if (!bmnz) {
            #pragma unroll
            for (int k = 0; k < KW; k++) {
                float xk = __ldg(&x[b * SEQ + tt * KW + k]);
                const float* PN = (xk > 0.0f) ? sP : sN;
                #pragma unroll
                for (int o = 0; o < 16; o++)
                    xt[o] = fmaf(xk, PN[o * 5 + k], xt[o]);
            }
        } else {
            #pragma unroll
            for (int k = 0; k < KW; k++) {
                float xk = __ldg(&x[b * SEQ + tt * KW + k]);
                #pragma unroll
                for (int i = 0; i < 16; i++) {
                    float f = fmaxf(fmaf(xk, sWm[i], sbm[i]), 0.0f);
                    const float4* wr = (const float4*)&sWcT[(i * KW + k) * 16];
                    #pragma unroll
                    for (int o4 = 0; o4 < 4; o4++) {
                        float4 w = wr[o4];
                        xt[o4 * 4 + 0] = fmaf(w.x, f, xt[o4 * 4 + 0]);
                        xt[o4 * 4 + 1] = fmaf(w.y, f, xt[o4 * 4 + 1]);
                        xt[o4 * 4 + 2] = fmaf(w.z, f, xt[o4 * 4 + 2]);
                        xt[o4 * 4 + 3] = fmaf(w.w, f, xt[o4 * 4 + 3]);
                    }
                }
            }
        }
        #pragma unroll
        for (int o = 0; o < 16; o++) xt[o] = sigf_exact(xt[o]);

        ull x2[16];
        #pragma unroll
        for (int o = 0; o < 16; o++) x2[o] = pk2(xt[o], xt[o]);

        float2* st = &stage[wrp][lane][0];
        ull q2 = 0ull;
        #pragma unroll
        for (int l = 0; l < 32; l += 2) {
            ull ya = fmul2(sWxT2[0][l],     x2[0]);
            ull yb = fmul2(sWxT2[0][l + 1], x2[0]);
            #pragma unroll
            for (int o = 1; o < 16; o++) {
                ya = ffma2(sWxT2[o][l],     x2[o], ya);
                yb = ffma2(sWxT2[o][l + 1], x2[o], yb);
            }
            float a0, a1, b0, b1;
            upk2(a0, a1, ya); upk2(b0, b1, yb);
            st[l]     = make_float2(a0, a1);
            st[l + 1] = make_float2(b0, b1);
            q2 = ffma2(ya, ya, q2);
            q2 = ffma2(yb, yb, q2);
        }
        float qa, qb;
        upk2(qa, qb, q2);
        float r = rsqrtf((qa + qb) * (1.0f / 64.0f) + 1e-5f);

        ull r2 = pk2(r, r);
        #pragma unroll
        for (int l = 0; l < 32; l++) {
            float2 v = st[l];
            ull tnorm = fmul2(pk2(v.x, v.y), r2);
            ull a2    = ffma2(tnorm, sgx2[l], sbxg2[l]);
            float a0, a1; upk2(a0, a1, a2);
            st[l] = make_float2(a0, a1);
        }
        __syncwarp();

        float2* gax2 = (float2*)g_ax;
        #pragma unroll 4
        for (int k = 0; k < 32; k++) {
            int tk = tbase + k;
            if (tk < T_STEPS)
                gax2[((size_t)tk * 256 + b) * 32 + lane] = stage[wrp][k][lane];
        }

        __syncthreads();
        if (threadIdx.x == 0) {
            __threadfence();
            st_rel(&g_flag[cx * 256 + b], 1);
        }
        return;
    }

    // ===================== SCAN ROLE (warp 0 only) =====================
    if (threadIdx.x >= 32) return;

    const unsigned ALL = 0xffffffffu;
    int lane  = threadIdx.x;
    int m     = lane & 15;
    bool upper = lane >= 16;
    int row   = blockIdx.x;

    __shared__ __align__(16) float  smean[16];
    __shared__ __align__(16) float  shv32[32];
    __shared__ __align__(16) float  sqp[32];
    __shared__ __align__(16) float2 scq32[32];

    {
        float s = 0.0f;
        #pragma unroll 8
        for (int j = 0; j < 64; j++) s += __ldg(&Wh[j * 16 + m]);
        if (!upper) smean[m] = s * (1.0f / 64.0f);
    }
    __syncwarp();

    float wa[16], wb[16];
    #pragma unroll
    for (int i = 0; i < 16; i++) {
        float cm = smean[i];
        wa[i] = __ldg(&Wh[lane * 16 + i]) - cm;
        wb[i] = __ldg(&Wh[(lane + 32) * 16 + i]) - cm;
    }
    float gha = gh[lane], ghb = gh[lane + 32];
    float bha = bh[lane], bhb = bh[lane + 32];
    float gcm = gc[m],    bcm = bc[m];

    float h = h0[row * 16 + m];
    float c = c0[row * 16 + m];

    uint32_t shv_w = smem_u32(shv32) + lane * 4;
    uint32_t shv_r = smem_u32(shv32) + 64;
    uint32_t sqp_w = smem_u32(sqp) + lane * 4;
    uint32_t sqp_r = smem_u32(sqp);
    uint32_t scq_w = smem_u32(scq32) + lane * 8;
    uint32_t scq_r = smem_u32(scq32) + 128;

    sts_f32(shv_w, h);

    const float2* ax = (const float2*)g_ax;
    const int stride = BATCH * 32;
    const int base = row * 32 + lane;
    float2 p0, p1;

    for (int ck = 0; ck < NCHUNK; ck++) {
        const int* fp = &g_flag[ck * 256 + row];
        while (ld_acq(fp) == 0) { }

        int tstart = ck * 128;
        p0 = ldg_cv_f2(ax + (size_t)tstart * stride + base);
        p1 = ldg_cv_f2(ax + (size_t)(tstart + 1) * stride + base);
        const float2* pf = ax + (size_t)(tstart + 2) * stride + base;

        int nsteps = (ck == NCHUNK - 1) ? (T_STEPS - 128 * (NCHUNK - 1)) : 128;

        #pragma unroll 2
        for (int k = 0; k < nsteps; k++) {
            float4 hv0 = lds_v4(shv_r);
            float4 hv1 = lds_v4(shv_r + 16);
            float4 hv2 = lds_v4(shv_r + 32);
            float4 hv3 = lds_v4(shv_r + 48);

            float2 cur = p0;
            p0 = p1;
            p1 = *pf;
            pf += stride;

            float ya0, ya1, yb0, yb1;
            ya0 = wa[0] * hv0.x; ya1 = wa[1] * hv0.y;
            yb0 = wb[0] * hv0.x; yb1 = wb[1] * hv0.y;
            ya0 = fmaf(wa[2],  hv0.z, ya0); ya1 = fmaf(wa[3],  hv0.w, ya1);
            yb0 = fmaf(wb[2],  hv0.z, yb0); yb1 = fmaf(wb[3],  hv0.w, yb1);
            ya0 = fmaf(wa[4],  hv1.x, ya0); ya1 = fmaf(wa[5],  hv1.y, ya1);
            yb0 = fmaf(wb[4],  hv1.x, yb0); yb1 = fmaf(wb[5],  hv1.y, yb1);
            ya0 = fmaf(wa[6],  hv1.z, ya0); ya1 = fmaf(wa[7],  hv1.w, ya1);
            yb0 = fmaf(wb[6],  hv1.z, yb0); yb1 = fmaf(wb[7],  hv1.w, yb1);
            ya0 = fmaf(wa[8],  hv2.x, ya0); ya1 = fmaf(wa[9],  hv2.y, ya1);
            yb0 = fmaf(wb[8],  hv2.x, yb0); yb1 = fmaf(wb[9],  hv2.y, yb1);
            ya0 = fmaf(wa[10], hv2.z, ya0); ya1 = fmaf(wa[11], hv2.w, ya1);
            yb0 = fmaf(wb[10], hv2.z, yb0); yb1 = fmaf(wb[11], hv2.w, yb1);
            ya0 = fmaf(wa[12], hv3.x, ya0); ya1 = fmaf(wa[13], hv3.y, ya1);
            yb0 = fmaf(wb[12], hv3.x, yb0); yb1 = fmaf(wb[13], hv3.y, yb1);
            ya0 = fmaf(wa[14], hv3.z, ya0); ya1 = fmaf(wa[15], hv3.w, ya1);
            yb0 = fmaf(wb[14], hv3.z, yb0); yb1 = fmaf(wb[15], hv3.w, yb1);
            float ya = ya0 + ya1;
            float yb = yb0 + yb1;

            sts_f32(sqp_w, fmaf(ya, ya, yb * yb));
            ull t0 = fadd2(lds_u64(sqp_r),       lds_u64(sqp_r + 8));
            ull t1 = fadd2(lds_u64(sqp_r + 16),  lds_u64(sqp_r + 24));
            ull t2 = fadd2(lds_u64(sqp_r + 32),  lds_u64(sqp_r + 40));
            ull t3 = fadd2(lds_u64(sqp_r + 48),  lds_u64(sqp_r + 56));
            ull t4 = fadd2(lds_u64(sqp_r + 64),  lds_u64(sqp_r + 72));
            ull t5 = fadd2(lds_u64(sqp_r + 80),  lds_u64(sqp_r + 88));
            ull t6 = fadd2(lds_u64(sqp_r + 96),  lds_u64(sqp_r + 104));
            ull t7 = fadd2(lds_u64(sqp_r + 112), lds_u64(sqp_r + 120));
            t0 = fadd2(t0, t1); t2 = fadd2(t2, t3);
            t4 = fadd2(t4, t5); t6 = fadd2(t6, t7);
            t0 = fadd2(fadd2(t0, t2), fadd2(t4, t6));
            float qlo, qhi; upk2(qlo, qhi, t0);
            float r = rsqrtf((qlo + qhi) * (1.0f / 64.0f) + 1e-5f);

            float ga = fmaf(ya * r, gha, bha) + cur.x;
            float gb = fmaf(yb * r, ghb, bhb) + cur.y;

            float u1 = fmaf(0.5f, tanhap(0.5f * ga), 0.5f);
            float tb = tanhap(upper ? (0.5f * gb) : gb);
            float u2 = upper ? fmaf(0.5f, tb, 0.5f) : tb;
            float Aval = u1 * u2;
            float A = __shfl_xor_sync(ALL, Aval, 16);

            c = fmaf(u1, c, A);
            sts_v2(scq_w, c, c * c);

            ull s0 = fadd2(lds_u64(scq_r),       lds_u64(scq_r + 8));
            ull s1 = fadd2(lds_u64(scq_r + 16),  lds_u64(scq_r + 24));
            ull s2 = fadd2(lds_u64(scq_r + 32),  lds_u64(scq_r + 40));
            ull s3 = fadd2(lds_u64(scq_r + 48),  lds_u64(scq_r + 56));
            ull s4 = fadd2(lds_u64(scq_r + 64),  lds_u64(scq_r + 72));
            ull s5 = fadd2(lds_u64(scq_r + 80),  lds_u64(scq_r + 88));
            ull s6 = fadd2(lds_u64(scq_r + 96),  lds_u64(scq_r + 104));
            ull s7 = fadd2(lds_u64(scq_r + 112), lds_u64(scq_r + 120));
            s0 = fadd2(s0, s1); s2 = fadd2(s2, s3);
            s4 = fadd2(s4, s5); s6 = fadd2(s6, s7);
            s0 = fadd2(fadd2(s0, s2), fadd2(s4, s6));
            float sc, qc; upk2(sc, qc, s0);

            float mc = sc * (1.0f / 16.0f);
            float vc = fmaf(-mc, mc, qc * (1.0f / 16.0f));
            float rc = rsqrtf(vc + 1e-5f);
            float cn = fmaf((c - mc) * rc, gcm, bcm);
            h = u2 * tanhap(cn);
            sts_f32(shv_w, h);
        }
    }

    // classifier
    float v = upper ? h * Wcls[m] : 0.0f;
    #pragma unroll
    for (int d = 16; d >= 1; d >>= 1)
        v += __shfl_xor_sync(ALL, v, d);
    if (lane == 0) {
        out[row] = sigf_exact(v + bcls[0]);
        atomicAdd(&g_flag[NFLAGS], 1);       // signal heaters
    }
}

// ---------------------------------------------------------------------------
extern "C" void kernel_launch(void* const* d_in, const int* in_sizes, int n_in,
                              void* d_out, int out_size)
{
    const float* x     = (const float*)d_in[0];
    const float* Wm    = (const float*)d_in[1];
    const float* bm    = (const float*)d_in[2];
    const float* Wc    = (const float*)d_in[3];
    const float* bconv = (const float*)d_in[4];
    const float* Wx    = (const float*)d_in[5];
    const float* Wh    = (const float*)d_in[6];
    const float* bg    = (const float*)d_in[7];
    const float* gx    = (const float*)d_in[8];
    const float* bx    = (const float*)d_in[9];
    const float* gh    = (const float*)d_in[10];
    const float* bh    = (const float*)d_in[11];
    const float* gc    = (const float*)d_in[12];
    const float* bc    = (const float*)d_in[13];
    const float* Wcls  = (const float*)d_in[14];
    const float* bcls  = (const float*)d_in[15];
    const float* h0    = (const float*)d_in[16];
    const float* c0    = (const float*)d_in[17];
    float* out = (float*)d_out;

    // zero chunk flags + done counter (graph-replay safe async memset node)
    void* flag_ptr = nullptr;
    cudaGetSymbolAddress(&flag_ptr, g_flag);
    cudaMemsetAsync(flag_ptr, 0, (NFLAGS + 1) * sizeof(int));

    fused_kernel<<<256 + NCHUNK * BATCH + NHEAT, 128>>>(
        x, Wm, bm, Wc, bconv, Wx, gx, bx, bg,
        Wh, gh, bh, gc, bc, Wcls, bcls, h0, c0, out);
}

// round 16
// speedup vs baseline: 1.0147x; 1.0147x over previous
#include <cuda_runtime.h>
#include <cstdint>

#define T_STEPS 2000
#define BATCH   256
#define SEQ     10000
#define KW      5
#define NCHUNK  16           // 16 chunks x 128 t (last chunk: 80 real steps)
#define NFLAGS  (NCHUNK * BATCH)
#define NSUB    4            // chunk-0 sub-flags (one per 32-t prepass warp)
#define NTOTALF (NFLAGS + NSUB * BATCH)

typedef unsigned long long ull;

// Gate pre-activations a_x[t][b][j], float2 at (t*256+b)*32 + l =
// { a[j=l], a[j=l+32] }. Padded by 2 timesteps for branchless prefetch.
__device__ float g_ax[(size_t)(T_STEPS + 2) * BATCH * 64];
// [0, NFLAGS): chunk flags (chunks 1..15 used);
// [NFLAGS, NFLAGS + 4*256): chunk-0 per-warp sub-flags [s*256 + b]
__device__ int g_flag[NTOTALF];

__device__ __forceinline__ float tanhap(float x) {
    float r; asm("tanh.approx.f32 %0, %1;" : "=f"(r) : "f"(x)); return r;
}

// ---- f32x2 packed helpers ----
__device__ __forceinline__ ull pk2(float lo, float hi) {
    ull r; asm("mov.b64 %0, {%1, %2};" : "=l"(r) : "f"(lo), "f"(hi)); return r;
}
__device__ __forceinline__ void upk2(float& lo, float& hi, ull v) {
    asm("mov.b64 {%0, %1}, %2;" : "=f"(lo), "=f"(hi) : "l"(v));
}
__device__ __forceinline__ ull ffma2(ull a, ull b, ull c) {
    ull r; asm("fma.rn.f32x2 %0, %1, %2, %3;" : "=l"(r) : "l"(a), "l"(b), "l"(c)); return r;
}
__device__ __forceinline__ ull fadd2(ull a, ull b) {
    ull r; asm("add.rn.f32x2 %0, %1, %2;" : "=l"(r) : "l"(a), "l"(b)); return r;
}
__device__ __forceinline__ ull fmul2(ull a, ull b) {
    ull r; asm("mul.rn.f32x2 %0, %1, %2;" : "=l"(r) : "l"(a), "l"(b)); return r;
}

__device__ __forceinline__ float sigf_exact(float x) {
    return __fdividef(1.0f, 1.0f + __expf(-x));
}

// ---- ordered smem access ----
__device__ __forceinline__ uint32_t smem_u32(const void* p) {
    uint32_t a;
    asm("{ .reg .u64 t; cvta.to.shared.u64 t, %1; cvt.u32.u64 %0, t; }"
        : "=r"(a) : "l"(p));
    return a;
}
__device__ __forceinline__ void sts_f32(uint32_t a, float v) {
    asm volatile("st.shared.f32 [%0], %1;" :: "r"(a), "f"(v) : "memory");
}
__device__ __forceinline__ void sts_v2(uint32_t a, float x, float y) {
    asm volatile("st.shared.v2.f32 [%0], {%1, %2};" :: "r"(a), "f"(x), "f"(y) : "memory");
}
__device__ __forceinline__ ull lds_u64(uint32_t a) {
    ull v; asm volatile("ld.shared.b64 %0, [%1];" : "=l"(v) : "r"(a) : "memory"); return v;
}
__device__ __forceinline__ float4 lds_v4(uint32_t a) {
    float4 v;
    asm volatile("ld.shared.v4.f32 {%0, %1, %2, %3}, [%4];"
                 : "=f"(v.x), "=f"(v.y), "=f"(v.z), "=f"(v.w) : "r"(a) : "memory");
    return v;
}

// ---- gpu-scope release/acquire flag ops + L1-bypass load ----
__device__ __forceinline__ int ld_acq(const int* p) {
    int v; asm volatile("ld.acquire.gpu.global.b32 %0, [%1];"
                        : "=r"(v) : "l"(p) : "memory"); return v;
}
__device__ __forceinline__ void st_rel(int* p, int v) {
    asm volatile("st.release.gpu.global.b32 [%0], %1;"
                 :: "l"(p), "r"(v) : "memory");
}
__device__ __forceinline__ float2 ldg_cv_f2(const float2* p) {
    float2 v;
    asm volatile("ld.global.cv.v2.f32 {%0, %1}, [%2];"
                 : "=f"(v.x), "=f"(v.y) : "l"(p) : "memory");
    return v;
}

// ===========================================================================
// Fused kernel: blocks [0,256) = scan rows (warp 0 only);
//               blocks [256, 256+4096) = prepass producers.
// Chunk-0 prepass blocks publish PER-WARP sub-flags (32-t granularity) so
// scan rows start ~4x earlier; chunks 1..15 use block-level flags.
// ===========================================================================
__global__ void __launch_bounds__(128) fused_kernel(
    const float* __restrict__ x,    const float* __restrict__ Wm,
    const float* __restrict__ bm,   const float* __restrict__ Wc,
    const float* __restrict__ bconv,const float* __restrict__ Wx,
    const float* __restrict__ gx,   const float* __restrict__ bx,
    const float* __restrict__ bg,
    const float* __restrict__ Wh,   const float* __restrict__ gh,
    const float* __restrict__ bh,   const float* __restrict__ gc,
    const float* __restrict__ bc,   const float* __restrict__ Wcls,
    const float* __restrict__ bcls, const float* __restrict__ h0,
    const float* __restrict__ c0,   float* __restrict__ out)
{
    if (blockIdx.x >= 256) {
        // ===================== PREPASS ROLE =====================
        __shared__ float sP[80], sN[80], sbc[16];
        __shared__ float sWm[16], sbm[16], scmx[16];
        __shared__ int   sbmnz;
        __shared__ float sWcT[80 * 16];
        __shared__ ull sWxT2[16][32];
        __shared__ ull sgx2[32], sbxg2[32];
        __shared__ float2 stage[4][32][33];

        int pb = blockIdx.x - 256;
        int cx = pb >> 8;          // chunk 0..15
        int b  = pb & 255;         // batch row

        if (threadIdx.x == 0) {
            int nz = 0;
            for (int i = 0; i < 16; i++) if (bm[i] != 0.0f) nz = 1;
            sbmnz = nz;
        }
        if (threadIdx.x < 80) {
            int o = threadIdx.x / 5, k = threadIdx.x % 5;
            float p = 0.0f, n = 0.0f;
            for (int i = 0; i < 16; i++) {
                float w = __ldg(&Wm[i]);
                float c = __ldg(&Wc[o * 80 + i * 5 + k]);
                if (w > 0.0f) p = fmaf(c, w, p);
                else if (w < 0.0f) n = fmaf(c, w, n);
            }
            sP[threadIdx.x] = p;
            sN[threadIdx.x] = n;
        }
        if (threadIdx.x >= 96 && threadIdx.x < 112) {
            int col = threadIdx.x - 96;
            float s = 0.0f;
            for (int j = 0; j < 64; j++) s += __ldg(&Wx[j * 16 + col]);
            scmx[col] = s * (1.0f / 64.0f);
        }
        for (int i = threadIdx.x; i < 16; i += blockDim.x) {
            sbc[i] = bconv[i]; sWm[i] = Wm[i]; sbm[i] = bm[i];
        }
        for (int i = threadIdx.x; i < 80 * 16; i += blockDim.x) {
            int ik = i >> 4, o = i & 15;
            sWcT[i] = Wc[o * 80 + ik];
        }
        for (int i = threadIdx.x; i < 32; i += blockDim.x) {
            sgx2[i]  = pk2(gx[i], gx[i + 32]);
            sbxg2[i] = pk2(bx[i] + bg[i], bx[i + 32] + bg[i + 32]);
        }
        __syncthreads();

        for (int i = threadIdx.x; i < 16 * 32; i += blockDim.x) {
            int o = i >> 5, l = i & 31;
            sWxT2[o][l] = pk2(Wx[l * 16 + o] - scmx[o],
                              Wx[(l + 32) * 16 + o] - scmx[o]);
        }
        __syncthreads();

        const int bmnz = sbmnz;
        int lane = threadIdx.x & 31;
        int wrp  = threadIdx.x >> 5;
        int tbase = cx * 128 + wrp * 32;
        int t     = tbase + lane;
        int tt = (t < T_STEPS) ? t : 0;

        float xt[16];
        #pragma unroll
        for (int o = 0; o < 16; o++) xt[o] = sbc[o];

        if (!bmnz) {
            #pragma unroll
            for (int k = 0; k < KW; k++) {
                float xk = __ldg(&x[b * SEQ + tt * KW + k]);
                const float* PN = (xk > 0.0f) ? sP : sN;
                #pragma unroll
                for (int o = 0; o < 16; o++)
                    xt[o] = fmaf(xk, PN[o * 5 + k], xt[o]);
            }
        } else {
            #pragma unroll
            for (int k = 0; k < KW; k++) {
                float xk = __ldg(&x[b * SEQ + tt * KW + k]);
                #pragma unroll
                for (int i = 0; i < 16; i++) {
                    float f = fmaxf(fmaf(xk, sWm[i], sbm[i]), 0.0f);
                    const float4* wr = (const float4*)&sWcT[(i * KW + k) * 16];
                    #pragma unroll
                    for (int o4 = 0; o4 < 4; o4++) {
                        float4 w = wr[o4];
                        xt[o4 * 4 + 0] = fmaf(w.x, f, xt[o4 * 4 + 0]);
                        xt[o4 * 4 + 1] = fmaf(w.y, f, xt[o4 * 4 + 1]);
                        xt[o4 * 4 + 2] = fmaf(w.z, f, xt[o4 * 4 + 2]);
                        xt[o4 * 4 + 3] = fmaf(w.w, f, xt[o4 * 4 + 3]);
                    }
                }
            }
        }
        #pragma unroll
        for (int o = 0; o < 16; o++) xt[o] = sigf_exact(xt[o]);

        ull x2[16];
        #pragma unroll
        for (int o = 0; o < 16; o++) x2[o] = pk2(xt[o], xt[o]);

        float2* st = &stage[wrp][lane][0];
        ull q2 = 0ull;
        #pragma unroll
        for (int l = 0; l < 32; l += 2) {
            ull ya = fmul2(sWxT2[0][l],     x2[0]);
            ull yb = fmul2(sWxT2[0][l + 1], x2[0]);
            #pragma unroll
            for (int o = 1; o < 16; o++) {
                ya = ffma2(sWxT2[o][l],     x2[o], ya);
                yb = ffma2(sWxT2[o][l + 1], x2[o], yb);
            }
            float a0, a1, b0, b1;
            upk2(a0, a1, ya); upk2(b0, b1, yb);
            st[l]     = make_float2(a0, a1);
            st[l + 1] = make_float2(b0, b1);
            q2 = ffma2(ya, ya, q2);
            q2 = ffma2(yb, yb, q2);
        }
        float qa, qb;
        upk2(qa, qb, q2);
        float r = rsqrtf((qa + qb) * (1.0f / 64.0f) + 1e-5f);

        ull r2 = pk2(r, r);
        #pragma unroll
        for (int l = 0; l < 32; l++) {
            float2 v = st[l];
            ull tnorm = fmul2(pk2(v.x, v.y), r2);
            ull a2    = ffma2(tnorm, sgx2[l], sbxg2[l]);
            float a0, a1; upk2(a0, a1, a2);
            st[l] = make_float2(a0, a1);
        }
        __syncwarp();

        float2* gax2 = (float2*)g_ax;
        #pragma unroll 4
        for (int k = 0; k < 32; k++) {
            int tk = tbase + k;
            if (tk < T_STEPS)
                gax2[((size_t)tk * 256 + b) * 32 + lane] = stage[wrp][k][lane];
        }

        if (cx == 0) {
            // per-warp sub-flag: this warp's 32 timesteps are fully written
            __syncwarp();
            if (lane == 0) {
                __threadfence();
                st_rel(&g_flag[NFLAGS + wrp * 256 + b], 1);
            }
        } else {
            __syncthreads();
            if (threadIdx.x == 0) {
                __threadfence();
                st_rel(&g_flag[cx * 256 + b], 1);
            }
        }
        return;
    }

    // ===================== SCAN ROLE (warp 0 only) =====================
    if (threadIdx.x >= 32) return;

    const unsigned ALL = 0xffffffffu;
    int lane  = threadIdx.x;
    int m     = lane & 15;
    bool upper = lane >= 16;
    int row   = blockIdx.x;

    __shared__ __align__(16) float  smean[16];
    __shared__ __align__(16) float  shv32[32];
    __shared__ __align__(16) float  sqp[32];
    __shared__ __align__(16) float2 scq32[32];

    {
        float s = 0.0f;
        #pragma unroll 8
        for (int j = 0; j < 64; j++) s += __ldg(&Wh[j * 16 + m]);
        if (!upper) smean[m] = s * (1.0f / 64.0f);
    }
    __syncwarp();

    float wa[16], wb[16];
    #pragma unroll
    for (int i = 0; i < 16; i++) {
        float cm = smean[i];
        wa[i] = __ldg(&Wh[lane * 16 + i]) - cm;
        wb[i] = __ldg(&Wh[(lane + 32) * 16 + i]) - cm;
    }
    float gha = gh[lane], ghb = gh[lane + 32];
    float bha = bh[lane], bhb = bh[lane + 32];
    float gcm = gc[m],    bcm = bc[m];

    float h = h0[row * 16 + m];
    float c = c0[row * 16 + m];

    uint32_t shv_w = smem_u32(shv32) + lane * 4;
    uint32_t shv_r = smem_u32(shv32) + 64;
    uint32_t sqp_w = smem_u32(sqp) + lane * 4;
    uint32_t sqp_r = smem_u32(sqp);
    uint32_t scq_w = smem_u32(scq32) + lane * 8;
    uint32_t scq_r = smem_u32(scq32) + 128;

    sts_f32(shv_w, h);

    const float2* ax = (const float2*)g_ax;
    const int stride = BATCH * 32;
    const int base = row * 32 + lane;
    float2 p0, p1;

    // 19 segments: 4 x 32-step sub-segments of chunk 0, then chunks 1..15.
    for (int seg = 0; seg < NSUB + (NCHUNK - 1); seg++) {
        int tstart, nsteps;
        const int* fp;
        if (seg < NSUB) {
            tstart = seg * 32;
            nsteps = 32;
            fp = &g_flag[NFLAGS + seg * 256 + row];
        } else {
            int ck = seg - NSUB + 1;
            tstart = ck * 128;
            nsteps = (ck == NCHUNK - 1) ? (T_STEPS - 128 * (NCHUNK - 1)) : 128;
            fp = &g_flag[ck * 256 + row];
        }
        while (ld_acq(fp) == 0) { }

        // reload prefetch regs with L1-bypassing loads (overshoot reads at the
        // previous segment boundary may be stale; .cv guarantees fresh data)
        p0 = ldg_cv_f2(ax + (size_t)tstart * stride + base);
        p1 = ldg_cv_f2(ax + (size_t)(tstart + 1) * stride + base);
        const float2* pf = ax + (size_t)(tstart + 2) * stride + base;

        #pragma unroll 2
        for (int k = 0; k < nsteps; k++) {
            float4 hv0 = lds_v4(shv_r);
            float4 hv1 = lds_v4(shv_r + 16);
            float4 hv2 = lds_v4(shv_r + 32);
            float4 hv3 = lds_v4(shv_r + 48);

            float2 cur = p0;
            p0 = p1;
            p1 = *pf;
            pf += stride;

            float ya0, ya1, yb0, yb1;
            ya0 = wa[0] * hv0.x; ya1 = wa[1] * hv0.y;
            yb0 = wb[0] * hv0.x; yb1 = wb[1] * hv0.y;
            ya0 = fmaf(wa[2],  hv0.z, ya0); ya1 = fmaf(wa[3],  hv0.w, ya1);
            yb0 = fmaf(wb[2],  hv0.z, yb0); yb1 = fmaf(wb[3],  hv0.w, yb1);
            ya0 = fmaf(wa[4],  hv1.x, ya0); ya1 = fmaf(wa[5],  hv1.y, ya1);
            yb0 = fmaf(wb[4],  hv1.x, yb0); yb1 = fmaf(wb[5],  hv1.y, yb1);
            ya0 = fmaf(wa[6],  hv1.z, ya0); ya1 = fmaf(wa[7],  hv1.w, ya1);
            yb0 = fmaf(wb[6],  hv1.z, yb0); yb1 = fmaf(wb[7],  hv1.w, yb1);
            ya0 = fmaf(wa[8],  hv2.x, ya0); ya1 = fmaf(wa[9],  hv2.y, ya1);
            yb0 = fmaf(wb[8],  hv2.x, yb0); yb1 = fmaf(wb[9],  hv2.y, yb1);
            ya0 = fmaf(wa[10], hv2.z, ya0); ya1 = fmaf(wa[11], hv2.w, ya1);
            yb0 = fmaf(wb[10], hv2.z, yb0); yb1 = fmaf(wb[11], hv2.w, yb1);
            ya0 = fmaf(wa[12], hv3.x, ya0); ya1 = fmaf(wa[13], hv3.y, ya1);
            yb0 = fmaf(wb[12], hv3.x, yb0); yb1 = fmaf(wb[13], hv3.y, yb1);
            ya0 = fmaf(wa[14], hv3.z, ya0); ya1 = fmaf(wa[15], hv3.w, ya1);
            yb0 = fmaf(wb[14], hv3.z, yb0); yb1 = fmaf(wb[15], hv3.w, yb1);
            float ya = ya0 + ya1;
            float yb = yb0 + yb1;

            sts_f32(sqp_w, fmaf(ya, ya, yb * yb));
            ull t0 = fadd2(lds_u64(sqp_r),       lds_u64(sqp_r + 8));
            ull t1 = fadd2(lds_u64(sqp_r + 16),  lds_u64(sqp_r + 24));
            ull t2 = fadd2(lds_u64(sqp_r + 32),  lds_u64(sqp_r + 40));
            ull t3 = fadd2(lds_u64(sqp_r + 48),  lds_u64(sqp_r + 56));
            ull t4 = fadd2(lds_u64(sqp_r + 64),  lds_u64(sqp_r + 72));
            ull t5 = fadd2(lds_u64(sqp_r + 80),  lds_u64(sqp_r + 88));
            ull t6 = fadd2(lds_u64(sqp_r + 96),  lds_u64(sqp_r + 104));
            ull t7 = fadd2(lds_u64(sqp_r + 112), lds_u64(sqp_r + 120));
            t0 = fadd2(t0, t1); t2 = fadd2(t2, t3);
            t4 = fadd2(t4, t5); t6 = fadd2(t6, t7);
            t0 = fadd2(fadd2(t0, t2), fadd2(t4, t6));
            float qlo, qhi; upk2(qlo, qhi, t0);
            float r = rsqrtf((qlo + qhi) * (1.0f / 64.0f) + 1e-5f);

            float ga = fmaf(ya * r, gha, bha) + cur.x;
            float gb = fmaf(yb * r, ghb, bhb) + cur.y;

            float u1 = fmaf(0.5f, tanhap(0.5f * ga), 0.5f);
            float tb = tanhap(upper ? (0.5f * gb) : gb);
            float u2 = upper ? fmaf(0.5f, tb, 0.5f) : tb;
            float Aval = u1 * u2;
            float A = __shfl_xor_sync(ALL, Aval, 16);

            c = fmaf(u1, c, A);
            sts_v2(scq_w, c, c * c);

            ull s0 = fadd2(lds_u64(scq_r),       lds_u64(scq_r + 8));
            ull s1 = fadd2(lds_u64(scq_r + 16),  lds_u64(scq_r + 24));
            ull s2 = fadd2(lds_u64(scq_r + 32),  lds_u64(scq_r + 40));
            ull s3 = fadd2(lds_u64(scq_r + 48),  lds_u64(scq_r + 56));
            ull s4 = fadd2(lds_u64(scq_r + 64),  lds_u64(scq_r + 72));
            ull s5 = fadd2(lds_u64(scq_r + 80),  lds_u64(scq_r + 88));
            ull s6 = fadd2(lds_u64(scq_r + 96),  lds_u64(scq_r + 104));
            ull s7 = fadd2(lds_u64(scq_r + 112), lds_u64(scq_r + 120));
            s0 = fadd2(s0, s1); s2 = fadd2(s2, s3);
            s4 = fadd2(s4, s5); s6 = fadd2(s6, s7);
            s0 = fadd2(fadd2(s0, s2), fadd2(s4, s6));
            float sc, qc; upk2(sc, qc, s0);

            float mc = sc * (1.0f / 16.0f);
            float vc = fmaf(-mc, mc, qc * (1.0f / 16.0f));
            float rc = rsqrtf(vc + 1e-5f);
            float cn = fmaf((c - mc) * rc, gcm, bcm);
            h = u2 * tanhap(cn);
            sts_f32(shv_w, h);
        }
    }

    // classifier
    float v = upper ? h * Wcls[m] : 0.0f;
    #pragma unroll
    for (int d = 16; d >= 1; d >>= 1)
        v += __shfl_xor_sync(ALL, v, d);
    if (lane == 0)
        out[row] = sigf_exact(v + bcls[0]);
}

// ---------------------------------------------------------------------------
extern "C" void kernel_launch(void* const* d_in, const int* in_sizes, int n_in,
                              void* d_out, int out_size)
{
    const float* x     = (const float*)d_in[0];
    const float* Wm    = (const float*)d_in[1];
    const float* bm    = (const float*)d_in[2];
    const float* Wc    = (const float*)d_in[3];
    const float* bconv = (const float*)d_in[4];
    const float* Wx    = (const float*)d_in[5];
    const float* Wh    = (const float*)d_in[6];
    const float* bg    = (const float*)d_in[7];
    const float* gx    = (const float*)d_in[8];
    const float* bx    = (const float*)d_in[9];
    const float* gh    = (const float*)d_in[10];
    const float* bh    = (const float*)d_in[11];
    const float* gc    = (const float*)d_in[12];
    const float* bc    = (const float*)d_in[13];
    const float* Wcls  = (const float*)d_in[14];
    const float* bcls  = (const float*)d_in[15];
    const float* h0    = (const float*)d_in[16];
    const float* c0    = (const float*)d_in[17];
    float* out = (float*)d_out;

    // zero all flags (graph-replay safe async memset node)
    void* flag_ptr = nullptr;
    cudaGetSymbolAddress(&flag_ptr, g_flag);
    cudaMemsetAsync(flag_ptr, 0, NTOTALF * sizeof(int));

    fused_kernel<<<256 + NCHUNK * BATCH, 128>>>(
        x, Wm, bm, Wc, bconv, Wx, gx, bx, bg,
        Wh, gh, bh, gc, bc, Wcls, bcls, h0, c0, out);
}